// round 6
// baseline (speedup 1.0000x reference)
#include <cuda_runtime.h>

// UnPooling: stride-2 zero-insertion unpool.
// in:  [B=32, H=112, W=112, C=64] fp32
// out: [B=32, 224, 224, 64] fp32; out[b, 2h, 2w, c] = in[b, h, w, c], else 0.
//
// Row-pair, output-driven mapping. Grid (7, 112, 32):
//   x = 512-float4 chunk within the row, y = INPUT row h (output rows
//   2h and 2h+1), z = batch.
// Each thread: up to 1 coalesced load (.cs) + 4 fully-contiguous stores:
//   even row  j0/j1 : data at even output pixels, zeros at odd pixels
//   odd  row  j0/j1 : zeros
// 4 independent stores per thread doubles store MLP vs R2; store stream
// stays perfectly linear per warp (R3 lesson: never interleave the 411MB
// store stream). .cs on both streams (R4: policy is neutral on ncu time,
// .cs marginally better wall).

constexpr int B     = 32;
constexpr int H     = 112;
constexpr int C4    = 16;          // 64 floats = 16 float4 per pixel
constexpr int OH    = 224;
constexpr int ROW4  = 224 * C4;    // 3584 float4 per output row
constexpr int IROW4 = 112 * C4;    // 1792 float4 per input row
constexpr int CHUNK = 512;         // float4 per block per row (2/thread/row)

__global__ void __launch_bounds__(256)
unpool_zi_kernel(const float4* __restrict__ in, float4* __restrict__ out)
{
    const unsigned tid  = threadIdx.x;
    const unsigned h    = blockIdx.y;          // input row
    const unsigned b    = blockIdx.z;
    const unsigned base = blockIdx.x * (unsigned)CHUNK + tid;

    float4* oeven = out + (size_t)(b * OH + 2u * h) * ROW4;
    float4* oodd  = oeven + ROW4;

    const float4 z = make_float4(0.f, 0.f, 0.f, 0.f);

    const float4* irow = in + (size_t)(b * H + h) * IROW4;

    const unsigned j0 = base;
    const unsigned j1 = base + 256u;

    const unsigned ow0 = j0 >> 4, c40 = j0 & 15u;
    const unsigned ow1 = j1 >> 4, c41 = j1 & 15u;

    float4 v0 = z, v1 = z;
    if (!(ow0 & 1u)) v0 = __ldcs(irow + (ow0 >> 1) * C4 + c40);
    if (!(ow1 & 1u)) v1 = __ldcs(irow + (ow1 >> 1) * C4 + c41);

    // 4 independent stores, all warp-contiguous 512B segments.
    __stcs(oeven + j0, v0);
    __stcs(oeven + j1, v1);
    __stcs(oodd  + j0, z);
    __stcs(oodd  + j1, z);
}

extern "C" void kernel_launch(void* const* d_in, const int* in_sizes, int n_in,
                              void* d_out, int out_size)
{
    const float4* in  = (const float4*)d_in[0];
    float4*       out = (float4*)d_out;

    dim3 grid(ROW4 / CHUNK, H, B);   // (7, 112, 32)
    unpool_zi_kernel<<<grid, 256>>>(in, out);
}